// round 1
// baseline (speedup 1.0000x reference)
#include <cuda_runtime.h>

// Problem constants: B=4, N=256, H=8, D=8, HD=64
#define BB   4
#define NN   256
#define HH   8
#define DD   8
#define HD   64
#define BN   (BB*NN)   // 1024

// Device scratch (no allocations allowed in kernel_launch)
__device__ float g_Q[BN * HD];
__device__ float g_K[BN * HD];   // pre-scaled by D^-0.5
__device__ float g_V[BN * HD];

// ---------------------------------------------------------------------------
// Kernel A: Q/K/V projections. One block per (b,n) row; 192 threads = 3 mats
// x 64 output channels. out[row,c] = sum_k h[row,k] * W[c,k]  (h @ W.T)
// ---------------------------------------------------------------------------
__global__ __launch_bounds__(192) void proj_kernel(
    const float* __restrict__ h,
    const float* __restrict__ Wq,
    const float* __restrict__ Wk,
    const float* __restrict__ Wv)
{
    int row = blockIdx.x;          // b*N + n
    int tid = threadIdx.x;
    __shared__ float hs[HD];

    if (tid < HD) hs[tid] = h[row * HD + tid];
    __syncthreads();

    int mat = tid / HD;            // 0=Q, 1=K, 2=V
    int c   = tid % HD;
    const float* W = (mat == 0) ? Wq : (mat == 1) ? Wk : Wv;

    const float4* Wr = reinterpret_cast<const float4*>(W + c * HD);
    const float4* hv = reinterpret_cast<const float4*>(hs);

    float acc = 0.f;
#pragma unroll
    for (int k = 0; k < HD / 4; k++) {
        float4 w = Wr[k];
        float4 x = hv[k];
        acc += w.x * x.x + w.y * x.y + w.z * x.z + w.w * x.w;
    }

    if (mat == 0)      g_Q[row * HD + c] = acc;
    else if (mat == 1) g_K[row * HD + c] = acc * 0.35355339059327373f; // D^-0.5
    else               g_V[row * HD + c] = acc;
}

// ---------------------------------------------------------------------------
// Kernel B: fused attention. One block per (b,i) row. 256 threads:
//   cg = tid & 15  -> 4-channel group (float4 over h*D+d), h = cg>>1
//   jg = tid >> 4  -> j-strided group (16 groups, j += 16)
// Streams e_att/e_value (64KB contiguous per block per array) exactly once.
// ---------------------------------------------------------------------------
__global__ __launch_bounds__(256) void attn_kernel(
    const float* __restrict__ e_att,
    const float* __restrict__ e_value,
    const float* __restrict__ mask,
    float* __restrict__ out)
{
    int bi  = blockIdx.x;          // b*N + i
    int b   = bi >> 8;
    int i   = bi & 255;
    int tid = threadIdx.x;

    __shared__ float q_sh[HD];
    __shared__ float qk_sh[NN * HH];     // [j][h], 8KB
    __shared__ float m_sh[NN];           // mask[b, j]
    __shared__ float red[16 * 16 * 8];   // [jg][cg][acc4|den4], 8KB

    if (tid < HD) q_sh[tid] = g_Q[bi * HD + tid];
    m_sh[tid] = mask[b * NN + tid];
    __syncthreads();

    // ---- per-block QK scores: qk[j][h] = Q[b,i,h,:] . K[b,j,h,:] (K pre-scaled)
    {
        int j = tid;               // 256 threads, one j each
        const float4* Kr = reinterpret_cast<const float4*>(g_K + (b * NN + j) * HD);
        const float4* Qr = reinterpret_cast<const float4*>(q_sh);
#pragma unroll
        for (int hh = 0; hh < HH; hh++) {
            float4 ka = Kr[hh * 2], kb = Kr[hh * 2 + 1];
            float4 qa = Qr[hh * 2], qb = Qr[hh * 2 + 1];
            float acc = ka.x * qa.x + ka.y * qa.y + ka.z * qa.z + ka.w * qa.w
                      + kb.x * qb.x + kb.y * qb.y + kb.z * qb.z + kb.w * qb.w;
            qk_sh[j * HH + hh] = acc;
        }
    }
    __syncthreads();

    int cg = tid & 15;
    int jg = tid >> 4;
    int hh = cg >> 1;              // head index for this channel group
    float mi = m_sh[i];

    const float4* ea4 = reinterpret_cast<const float4*>(e_att)   + (size_t)bi * NN * 16;
    const float4* ev4 = reinterpret_cast<const float4*>(e_value) + (size_t)bi * NN * 16;
    const float4* v4  = reinterpret_cast<const float4*>(g_V)     + (size_t)b * NN * 16;

    float4 acc = make_float4(0.f, 0.f, 0.f, 0.f);
    float4 den = make_float4(0.f, 0.f, 0.f, 0.f);

#pragma unroll 4
    for (int j = jg; j < NN; j += 16) {
        float4 ea = ea4[j * 16 + cg];
        float4 ev = ev4[j * 16 + cg];
        float4 v  = v4 [j * 16 + cg];
        float qk  = qk_sh[j * HH + hh];
        float m   = mi * m_sh[j];

        // s0 = exp(clip(qk + e_att, -5, 5)); den += s0*m; acc += s0*m^2*(V+e_value)
        float s0x = __expf(fminf(fmaxf(qk + ea.x, -5.f), 5.f));
        float s0y = __expf(fminf(fmaxf(qk + ea.y, -5.f), 5.f));
        float s0z = __expf(fminf(fmaxf(qk + ea.z, -5.f), 5.f));
        float s0w = __expf(fminf(fmaxf(qk + ea.w, -5.f), 5.f));

        float smx = s0x * m, smy = s0y * m, smz = s0z * m, smw = s0w * m;
        den.x += smx; den.y += smy; den.z += smz; den.w += smw;

        acc.x += smx * m * (v.x + ev.x);
        acc.y += smy * m * (v.y + ev.y);
        acc.z += smz * m * (v.z + ev.z);
        acc.w += smw * m * (v.w + ev.w);
    }

    float* r = &red[(jg * 16 + cg) * 8];
    r[0] = acc.x; r[1] = acc.y; r[2] = acc.z; r[3] = acc.w;
    r[4] = den.x; r[5] = den.y; r[6] = den.z; r[7] = den.w;
    __syncthreads();

    if (tid < HD) {
        int c   = tid;
        int cgr = c >> 2;
        int k   = c & 3;
        float a = 0.f, d = 0.f;
#pragma unroll
        for (int g = 0; g < 16; g++) {
            a += red[(g * 16 + cgr) * 8 + k];
            d += red[(g * 16 + cgr) * 8 + 4 + k];
        }
        out[(size_t)bi * HD + c] = a / fmaxf(d, 1e-6f);
    }
}

// ---------------------------------------------------------------------------
extern "C" void kernel_launch(void* const* d_in, const int* in_sizes, int n_in,
                              void* d_out, int out_size)
{
    const float* h       = (const float*)d_in[0];
    const float* e_att   = (const float*)d_in[1];
    const float* e_value = (const float*)d_in[2];
    const float* mask    = (const float*)d_in[3];
    const float* Wq      = (const float*)d_in[4];
    const float* Wk      = (const float*)d_in[5];
    const float* Wv      = (const float*)d_in[6];
    float* out           = (float*)d_out;

    proj_kernel<<<BN, 192>>>(h, Wq, Wk, Wv);
    attn_kernel<<<BN, 256>>>(e_att, e_value, mask, out);
}

// round 2
// speedup vs baseline: 1.1349x; 1.1349x over previous
#include <cuda_runtime.h>
#include <cstdint>

// Problem constants: B=4, N=256, H=8, D=8, HD=64
#define BB   4
#define NN   256
#define HH   8
#define HD   64
#define BN   (BB*NN)     // 1024
#define TJ   16          // j per tile
#define NT   (NN/TJ)     // 16 tiles
#define ST   2           // pipeline stages
#define TILE_F (TJ*HD)   // 1024 floats per tile per array
#define TILE_B (TILE_F*4)// 4096 bytes

// Device scratch (no allocations allowed)
__device__ float g_Q[BN * HD];
__device__ float g_K[BN * HD];   // pre-scaled by D^-0.5
__device__ float g_V[BN * HD];

// ---------------------------------------------------------------------------
// PTX helpers
// ---------------------------------------------------------------------------
__device__ __forceinline__ uint32_t s2u(const void* p) {
    return (uint32_t)__cvta_generic_to_shared(p);
}
__device__ __forceinline__ void mbar_init(uint32_t mbar, uint32_t count) {
    asm volatile("mbarrier.init.shared::cta.b64 [%0], %1;" :: "r"(mbar), "r"(count) : "memory");
}
__device__ __forceinline__ void mbar_expect_tx(uint32_t mbar, uint32_t bytes) {
    asm volatile("mbarrier.arrive.expect_tx.shared::cta.b64 _, [%0], %1;"
                 :: "r"(mbar), "r"(bytes) : "memory");
}
__device__ __forceinline__ void mbar_wait(uint32_t mbar, uint32_t parity) {
    uint32_t done = 0;
    while (!done) {
        asm volatile("{\n\t.reg .pred p;\n\t"
                     "mbarrier.try_wait.parity.acquire.cta.shared::cta.b64 p, [%1], %2, 0x989680;\n\t"
                     "selp.b32 %0, 1, 0, p;\n\t}"
                     : "=r"(done) : "r"(mbar), "r"(parity) : "memory");
    }
}
__device__ __forceinline__ void bulk_g2s(uint32_t dst, const void* src, uint32_t bytes, uint32_t mbar) {
    asm volatile("cp.async.bulk.shared::cluster.global.mbarrier::complete_tx::bytes "
                 "[%0], [%1], %2, [%3];"
                 :: "r"(dst), "l"(src), "r"(bytes), "r"(mbar) : "memory");
}
__device__ __forceinline__ void fence_async_proxy() {
    asm volatile("fence.proxy.async.shared::cta;" ::: "memory");
}

// ---------------------------------------------------------------------------
// Kernel A: Q/K/V projections. 128 blocks x 192 threads, 8 rows per block.
// W staged in smem once per block (48KB). out[row,c] = sum_k h[row,k]*W[c,k]
// ---------------------------------------------------------------------------
__global__ __launch_bounds__(192) void proj_kernel(
    const float* __restrict__ h,
    const float* __restrict__ Wq,
    const float* __restrict__ Wk,
    const float* __restrict__ Wv)
{
    __shared__ float Wsh[3 * HD * HD];   // 48KB
    int tid = threadIdx.x;

    // Stage all three weight matrices: 3072 float4 / 192 threads = 16 each
    for (int idx = tid; idx < 3 * 1024; idx += 192) {
        float4 val;
        if (idx < 1024)      val = reinterpret_cast<const float4*>(Wq)[idx];
        else if (idx < 2048) val = reinterpret_cast<const float4*>(Wk)[idx - 1024];
        else                 val = reinterpret_cast<const float4*>(Wv)[idx - 2048];
        reinterpret_cast<float4*>(Wsh)[idx] = val;
    }
    __syncthreads();

    int mat = tid / HD;            // 0=Q, 1=K, 2=V
    int c   = tid % HD;
    const float4* Wr = reinterpret_cast<const float4*>(Wsh + mat * 4096 + c * HD);
    float scale = (mat == 1) ? 0.35355339059327373f : 1.0f;
    float* dst = (mat == 0) ? g_Q : (mat == 1) ? g_K : g_V;

    int row0 = blockIdx.x * 8;
#pragma unroll
    for (int r = 0; r < 8; r++) {
        int row = row0 + r;
        const float4* hv = reinterpret_cast<const float4*>(h + row * HD);
        float acc = 0.f;
#pragma unroll
        for (int k = 0; k < 16; k++) {
            int kk = (k + c) & 15;           // skew to avoid smem bank conflicts
            float4 w = Wr[kk];
            float4 x = hv[kk];
            acc += w.x * x.x + w.y * x.y + w.z * x.z + w.w * x.w;
        }
        dst[row * HD + c] = acc * scale;
    }
}

// ---------------------------------------------------------------------------
// Kernel B: fused attention, bulk-async pipelined.
// One block per (b,i). 256 threads: tid = jg*16 + cg (jg in [0,16), cg in [0,16)).
// Tile t covers j in [16t, 16t+16); thread handles j = 16t+jg, channels 4cg..4cg+3.
// e_att/e_value/V j-tiles (3 x 4KB, contiguous) stream via cp.async.bulk.
// ---------------------------------------------------------------------------
__global__ __launch_bounds__(256, 5) void attn_kernel(
    const float* __restrict__ e_att,
    const float* __restrict__ e_value,
    const float* __restrict__ mask,
    float* __restrict__ out)
{
    int bi  = blockIdx.x;
    int b   = bi >> 8;
    int i   = bi & 255;
    int tid = threadIdx.x;

    __shared__ __align__(128) float ea_t[ST][TILE_F];
    __shared__ __align__(128) float ev_t[ST][TILE_F];
    __shared__ __align__(128) float v_t [ST][TILE_F];
    __shared__ float qk_sh[NN * HH];          // [j][h]  8KB
    __shared__ float m_sh[NN];
    __shared__ float q_sh[HD];
    __shared__ float red[8][16][8];           // [warp][cg][acc4|den4]  4KB
    __shared__ __align__(8) unsigned long long mbar[ST];

    uint32_t mb0 = s2u(&mbar[0]);
    const char* ea_g = reinterpret_cast<const char*>(e_att)   + (size_t)bi * NN * HD * 4;
    const char* ev_g = reinterpret_cast<const char*>(e_value) + (size_t)bi * NN * HD * 4;
    const char* v_g  = reinterpret_cast<const char*>(g_V)     + (size_t)b  * NN * HD * 4;

    if (tid == 0) {
        mbar_init(mb0, 1);
        mbar_init(mb0 + 8, 1);
        fence_async_proxy();
        // prime stages 0 and 1 (tiles 0 and 1)
#pragma unroll
        for (int t = 0; t < ST; t++) {
            uint32_t mb = mb0 + t * 8;
            mbar_expect_tx(mb, 3 * TILE_B);
            bulk_g2s(s2u(&ea_t[t][0]), ea_g + (size_t)t * TILE_B, TILE_B, mb);
            bulk_g2s(s2u(&ev_t[t][0]), ev_g + (size_t)t * TILE_B, TILE_B, mb);
            bulk_g2s(s2u(&v_t [t][0]), v_g  + (size_t)t * TILE_B, TILE_B, mb);
        }
    }

    if (tid < HD) q_sh[tid] = g_Q[bi * HD + tid];
    m_sh[tid] = mask[b * NN + tid];
    __syncthreads();

    // ---- QK scores (overlapped with TMA prefetch): qk[j][h] = Q . K (K pre-scaled)
    {
        int j = tid;
        const float4* Kr = reinterpret_cast<const float4*>(g_K + (b * NN + j) * HD);
        const float4* Qr = reinterpret_cast<const float4*>(q_sh);
#pragma unroll
        for (int hh = 0; hh < HH; hh++) {
            float4 ka = Kr[hh * 2], kb = Kr[hh * 2 + 1];
            float4 qa = Qr[hh * 2], qb = Qr[hh * 2 + 1];
            qk_sh[j * HH + hh] =
                  ka.x * qa.x + ka.y * qa.y + ka.z * qa.z + ka.w * qa.w
                + kb.x * qb.x + kb.y * qb.y + kb.z * qb.z + kb.w * qb.w;
        }
    }
    __syncthreads();

    int cg = tid & 15;
    int jg = tid >> 4;
    int hh = cg >> 1;
    float mi = m_sh[i];

    float4 acc = make_float4(0.f, 0.f, 0.f, 0.f);
    float4 den = make_float4(0.f, 0.f, 0.f, 0.f);

    for (int t = 0; t < NT; t++) {
        int s = t & (ST - 1);
        uint32_t mb = mb0 + s * 8;
        mbar_wait(mb, (t >> 1) & 1);

        float4 ea = reinterpret_cast<const float4*>(ea_t[s])[tid];
        float4 ev = reinterpret_cast<const float4*>(ev_t[s])[tid];
        float4 v  = reinterpret_cast<const float4*>(v_t [s])[tid];
        int j = t * TJ + jg;
        float qk = qk_sh[j * HH + hh];
        float m  = mi * m_sh[j];

        float s0x = __expf(fminf(fmaxf(qk + ea.x, -5.f), 5.f));
        float s0y = __expf(fminf(fmaxf(qk + ea.y, -5.f), 5.f));
        float s0z = __expf(fminf(fmaxf(qk + ea.z, -5.f), 5.f));
        float s0w = __expf(fminf(fmaxf(qk + ea.w, -5.f), 5.f));

        float smx = s0x * m, smy = s0y * m, smz = s0z * m, smw = s0w * m;
        den.x += smx; den.y += smy; den.z += smz; den.w += smw;
        acc.x += smx * m * (v.x + ev.x);
        acc.y += smy * m * (v.y + ev.y);
        acc.z += smz * m * (v.z + ev.z);
        acc.w += smw * m * (v.w + ev.w);

        __syncthreads();   // all threads done reading stage s

        if (tid == 0 && t + ST < NT) {
            int tn = t + ST;
            mbar_expect_tx(mb, 3 * TILE_B);
            bulk_g2s(s2u(&ea_t[s][0]), ea_g + (size_t)tn * TILE_B, TILE_B, mb);
            bulk_g2s(s2u(&ev_t[s][0]), ev_g + (size_t)tn * TILE_B, TILE_B, mb);
            bulk_g2s(s2u(&v_t [s][0]), v_g  + (size_t)tn * TILE_B, TILE_B, mb);
        }
    }

    // ---- reduce the jg pair within each warp (lanes L and L^16 share cg)
    acc.x += __shfl_xor_sync(0xffffffffu, acc.x, 16);
    acc.y += __shfl_xor_sync(0xffffffffu, acc.y, 16);
    acc.z += __shfl_xor_sync(0xffffffffu, acc.z, 16);
    acc.w += __shfl_xor_sync(0xffffffffu, acc.w, 16);
    den.x += __shfl_xor_sync(0xffffffffu, den.x, 16);
    den.y += __shfl_xor_sync(0xffffffffu, den.y, 16);
    den.z += __shfl_xor_sync(0xffffffffu, den.z, 16);
    den.w += __shfl_xor_sync(0xffffffffu, den.w, 16);

    if ((tid & 16) == 0) {
        int w = tid >> 5;
        float* r = &red[w][cg][0];
        r[0] = acc.x; r[1] = acc.y; r[2] = acc.z; r[3] = acc.w;
        r[4] = den.x; r[5] = den.y; r[6] = den.z; r[7] = den.w;
    }
    __syncthreads();

    if (tid < HD) {
        int c   = tid;
        int cgr = c >> 2;
        int k   = c & 3;
        float a = 0.f, d = 0.f;
#pragma unroll
        for (int w = 0; w < 8; w++) {
            a += red[w][cgr][k];
            d += red[w][cgr][4 + k];
        }
        out[(size_t)bi * HD + c] = a / fmaxf(d, 1e-6f);
    }
}

// ---------------------------------------------------------------------------
extern "C" void kernel_launch(void* const* d_in, const int* in_sizes, int n_in,
                              void* d_out, int out_size)
{
    const float* h       = (const float*)d_in[0];
    const float* e_att   = (const float*)d_in[1];
    const float* e_value = (const float*)d_in[2];
    const float* mask    = (const float*)d_in[3];
    const float* Wq      = (const float*)d_in[4];
    const float* Wk      = (const float*)d_in[5];
    const float* Wv      = (const float*)d_in[6];
    float* out           = (float*)d_out;

    proj_kernel<<<BN / 8, 192>>>(h, Wq, Wk, Wv);
    attn_kernel<<<BN, 256>>>(e_att, e_value, mask, out);
}